// round 3
// baseline (speedup 1.0000x reference)
#include <cuda_runtime.h>
#include <cuda_bf16.h>
#include <math_constants.h>

#define E  512
#define L  1024
#define B2 512

__device__ float g_v[E];
__device__ float g_c;
__device__ float g_scores[B2 * L];        // raw attention energies
__device__ float g_partial[128 * E];      // prep stage-A partials

// ---------------------------------------------------------------------------
// Prep stage A: block j reduces rows f in [4j, 4j+4), fully coalesced.
// partial[j][e] = sum_{f in block} W[f][e] * wv[f]
// ---------------------------------------------------------------------------
__global__ __launch_bounds__(128)
void prep_partial(const float* __restrict__ W,
                  const float* __restrict__ wv) {
    const int j = blockIdx.x;           // 0..127
    const int t = threadIdx.x;          // 0..127, owns float4 at e = 4t
    const int f0 = j * 4;

    float4 acc = make_float4(0.f, 0.f, 0.f, 0.f);
    #pragma unroll
    for (int r = 0; r < 4; ++r) {
        const float s = __ldg(wv + f0 + r);
        const float4 a = __ldg(reinterpret_cast<const float4*>(
                                   W + (size_t)(f0 + r) * E) + t);
        acc.x = fmaf(a.x, s, acc.x);
        acc.y = fmaf(a.y, s, acc.y);
        acc.z = fmaf(a.z, s, acc.z);
        acc.w = fmaf(a.w, s, acc.w);
    }
    reinterpret_cast<float4*>(g_partial + (size_t)j * E)[t] = acc;
}

// ---------------------------------------------------------------------------
// Prep stage B: fold 128 partials into g_v (4 blocks x 128 e each, coalesced);
// block 0 also computes c = bias . wv.
// ---------------------------------------------------------------------------
__global__ __launch_bounds__(128)
void prep_reduce(const float* __restrict__ bias,
                 const float* __restrict__ wv) {
    __shared__ float s_red[4];
    const int t = threadIdx.x;
    const int e = blockIdx.x * 128 + t;

    float s = 0.f;
    #pragma unroll 8
    for (int j = 0; j < 128; ++j)
        s += g_partial[j * E + e];
    g_v[e] = s;

    if (blockIdx.x == 0) {
        const int warp = t >> 5, lane = t & 31;
        float part = 0.f;
        #pragma unroll
        for (int f = t; f < E; f += 128)
            part = fmaf(__ldg(bias + f), __ldg(wv + f), part);
        #pragma unroll
        for (int o = 16; o; o >>= 1)
            part += __shfl_down_sync(0xffffffffu, part, o);
        if (lane == 0) s_red[warp] = part;
        __syncthreads();
        if (t == 0)
            g_c = s_red[0] + s_red[1] + s_red[2] + s_red[3];
    }
}

// ---------------------------------------------------------------------------
// Scores: grid (L/128, B2), 256 threads = 8 warps, 16 tokens per warp.
// Fully unrolled 16-token batch: all loads independent of the shuffle
// reductions, which are batched at the end (16 independent trees).
// ---------------------------------------------------------------------------
#define CHUNK 128
#define TPW   16    // tokens per warp

__global__ __launch_bounds__(256, 4)
void scores_kernel(const float* __restrict__ q,
                   const int* __restrict__ lens) {
    __shared__ float s_v[E];

    const int tid  = threadIdx.x;
    const int warp = tid >> 5;
    const int lane = tid & 31;
    const int b    = blockIdx.y;
    const int base = blockIdx.x * CHUNK;
    const int len  = lens[b];

    if (base >= len) return;             // whole chunk masked

    #pragma unroll
    for (int i = tid; i < E; i += 256) s_v[i] = g_v[i];
    __syncthreads();

    const float4* __restrict__ vv  = reinterpret_cast<const float4*>(s_v);
    const float*  __restrict__ qrow = q + (size_t)b * L * E;
    const int tok_end = min(base + CHUNK, len);
    const int l0 = base + warp * TPW;
    const int nt = tok_end - l0;         // tokens this warp actually owns
    if (nt <= 0) return;

    // stage v float4s for this lane once
    float4 w0 = vv[lane];
    float4 w1 = vv[32 + lane];
    float4 w2 = vv[64 + lane];
    float4 w3 = vv[96 + lane];

    float acc[TPW];
    #pragma unroll
    for (int t = 0; t < TPW; ++t) acc[t] = 0.f;

    #pragma unroll
    for (int t = 0; t < TPW; ++t) {
        if (t < nt) {
            const float4* __restrict__ qp =
                reinterpret_cast<const float4*>(qrow + (size_t)(l0 + t) * E);
            float4 a0 = __ldg(qp + lane);
            float4 a1 = __ldg(qp + 32 + lane);
            float4 a2 = __ldg(qp + 64 + lane);
            float4 a3 = __ldg(qp + 96 + lane);
            float r = 0.f;
            r = fmaf(a0.x, w0.x, r); r = fmaf(a0.y, w0.y, r);
            r = fmaf(a0.z, w0.z, r); r = fmaf(a0.w, w0.w, r);
            r = fmaf(a1.x, w1.x, r); r = fmaf(a1.y, w1.y, r);
            r = fmaf(a1.z, w1.z, r); r = fmaf(a1.w, w1.w, r);
            r = fmaf(a2.x, w2.x, r); r = fmaf(a2.y, w2.y, r);
            r = fmaf(a2.z, w2.z, r); r = fmaf(a2.w, w2.w, r);
            r = fmaf(a3.x, w3.x, r); r = fmaf(a3.y, w3.y, r);
            r = fmaf(a3.z, w3.z, r); r = fmaf(a3.w, w3.w, r);
            acc[t] = r;
        }
    }

    const float cc = g_c;
    #pragma unroll
    for (int t = 0; t < TPW; ++t) {
        float v = acc[t];
        #pragma unroll
        for (int o = 16; o; o >>= 1)
            v += __shfl_down_sync(0xffffffffu, v, o);
        if (lane == 0 && t < nt)
            g_scores[b * L + l0 + t] = v + cc;
    }
}

// ---------------------------------------------------------------------------
// Softmax over valid prefix of each row.
// ---------------------------------------------------------------------------
__global__ __launch_bounds__(1024)
void softmax_kernel(const int* __restrict__ lens,
                    float* __restrict__ out) {
    __shared__ float s_red[32];
    __shared__ float s_bcast;

    const int tid  = threadIdx.x;
    const int warp = tid >> 5;
    const int lane = tid & 31;
    const int b    = blockIdx.x;
    const int len  = lens[b];

    float val = (tid < len) ? g_scores[b * L + tid] : -CUDART_INF_F;

    float m = val;
    #pragma unroll
    for (int o = 16; o; o >>= 1)
        m = fmaxf(m, __shfl_down_sync(0xffffffffu, m, o));
    if (lane == 0) s_red[warp] = m;
    __syncthreads();
    if (warp == 0) {
        float t = s_red[lane];
        #pragma unroll
        for (int o = 16; o; o >>= 1)
            t = fmaxf(t, __shfl_down_sync(0xffffffffu, t, o));
        if (lane == 0) s_bcast = t;
    }
    __syncthreads();
    const float rowmax = s_bcast;

    float e = (tid < len) ? expf(val - rowmax) : 0.f;

    float s = e;
    #pragma unroll
    for (int o = 16; o; o >>= 1)
        s += __shfl_down_sync(0xffffffffu, s, o);
    __syncthreads();
    if (lane == 0) s_red[warp] = s;
    __syncthreads();
    if (warp == 0) {
        float t = s_red[lane];
        #pragma unroll
        for (int o = 16; o; o >>= 1)
            t += __shfl_down_sync(0xffffffffu, t, o);
        if (lane == 0) s_bcast = t;
    }
    __syncthreads();

    out[(size_t)b * L + tid] = e / s_bcast;
}

extern "C" void kernel_launch(void* const* d_in, const int* in_sizes, int n_in,
                              void* d_out, int out_size) {
    const float* questions = (const float*)d_in[0];   // [B2, L, E]
    const int*   lens      = (const int*)d_in[1];     // [B2]
    const float* W         = (const float*)d_in[2];   // [E, E]
    const float* bias      = (const float*)d_in[3];   // [E]
    const float* wv        = (const float*)d_in[4];   // [E, 1]
    float* out             = (float*)d_out;           // [B2, L]

    prep_partial<<<128, 128>>>(W, wv);
    prep_reduce<<<4, 128>>>(bias, wv);
    dim3 sgrid(L / CHUNK, B2);
    scores_kernel<<<sgrid, 256>>>(questions, lens);
    softmax_kernel<<<B2, 1024>>>(lens, out);
}

// round 4
// speedup vs baseline: 1.0208x; 1.0208x over previous
#include <cuda_runtime.h>
#include <cuda_bf16.h>
#include <math_constants.h>

#define E  512
#define L  1024
#define B2 512
#define CHUNK  128
#define NCHUNK (L / CHUNK)     // 8 chunk-CTAs per row

__device__ float g_v[E];
__device__ float g_c;
__device__ float g_scores[B2 * L];     // raw attention energies
__device__ float g_partial[128 * E];   // prep stage-A partials
__device__ int   g_done[B2];           // per-row arrival counters

// ---------------------------------------------------------------------------
// Prep stage A: block j reduces rows f in [4j, 4j+4), fully coalesced.
// ---------------------------------------------------------------------------
__global__ __launch_bounds__(128)
void prep_partial(const float* __restrict__ W,
                  const float* __restrict__ wv) {
    const int j = blockIdx.x;           // 0..127
    const int t = threadIdx.x;          // 0..127
    const int f0 = j * 4;

    float4 acc = make_float4(0.f, 0.f, 0.f, 0.f);
    #pragma unroll
    for (int r = 0; r < 4; ++r) {
        const float s = __ldg(wv + f0 + r);
        const float4 a = __ldg(reinterpret_cast<const float4*>(
                                   W + (size_t)(f0 + r) * E) + t);
        acc.x = fmaf(a.x, s, acc.x);
        acc.y = fmaf(a.y, s, acc.y);
        acc.z = fmaf(a.z, s, acc.z);
        acc.w = fmaf(a.w, s, acc.w);
    }
    reinterpret_cast<float4*>(g_partial + (size_t)j * E)[t] = acc;
}

// ---------------------------------------------------------------------------
// Prep stage B: fold partials into g_v; compute c; reset arrival counters.
// ---------------------------------------------------------------------------
__global__ __launch_bounds__(128)
void prep_reduce(const float* __restrict__ bias,
                 const float* __restrict__ wv) {
    __shared__ float s_red[4];
    const int t = threadIdx.x;
    const int e = blockIdx.x * 128 + t;

    g_done[e & (B2 - 1)] = 0;           // 4*128 = 512 resets

    float s = 0.f;
    #pragma unroll 8
    for (int j = 0; j < 128; ++j)
        s += g_partial[j * E + e];
    g_v[e] = s;

    if (blockIdx.x == 0) {
        const int warp = t >> 5, lane = t & 31;
        float part = 0.f;
        #pragma unroll
        for (int f = t; f < E; f += 128)
            part = fmaf(__ldg(bias + f), __ldg(wv + f), part);
        #pragma unroll
        for (int o = 16; o; o >>= 1)
            part += __shfl_down_sync(0xffffffffu, part, o);
        if (lane == 0) s_red[warp] = part;
        __syncthreads();
        if (t == 0)
            g_c = s_red[0] + s_red[1] + s_red[2] + s_red[3];
    }
}

// ---------------------------------------------------------------------------
// Scores + fused tail softmax.
// grid = (NCHUNK, B2), 256 threads = 8 warps, 16 tokens per warp.
// The last chunk-CTA to arrive for a row performs the row's softmax.
// ---------------------------------------------------------------------------
__global__ __launch_bounds__(256)
void scores_kernel(const float* __restrict__ q,
                   const int* __restrict__ lens,
                   float* __restrict__ out) {
    __shared__ float s_v[E];
    __shared__ float s_red[8];
    __shared__ float s_bcast;
    __shared__ int   s_last;

    const int tid  = threadIdx.x;
    const int warp = tid >> 5;
    const int lane = tid & 31;
    const int b    = blockIdx.y;
    const int base = blockIdx.x * CHUNK;
    const int len  = lens[b];

    // ---- score phase (R2-proven inner loop) ----
    if (base < len) {
        #pragma unroll
        for (int i = tid; i < E; i += 256) s_v[i] = g_v[i];
        __syncthreads();

        const float c = g_c;
        const float4* __restrict__ vv  = reinterpret_cast<const float4*>(s_v);
        const float*  __restrict__ qrow = q + (size_t)b * L * E;
        const int tok_end = min(base + CHUNK, len);

        for (int l = base + warp * 16; l < min(base + warp * 16 + 16, tok_end); ++l) {
            const float4* __restrict__ qp =
                reinterpret_cast<const float4*>(qrow + (size_t)l * E);
            float acc = 0.f;
            #pragma unroll
            for (int k = 0; k < 4; ++k) {
                float4 a = __ldg(qp + k * 32 + lane);
                float4 w = vv[k * 32 + lane];
                acc = fmaf(a.x, w.x, acc);
                acc = fmaf(a.y, w.y, acc);
                acc = fmaf(a.z, w.z, acc);
                acc = fmaf(a.w, w.w, acc);
            }
            #pragma unroll
            for (int o = 16; o; o >>= 1)
                acc += __shfl_down_sync(0xffffffffu, acc, o);
            if (lane == 0) g_scores[b * L + l] = acc + c;
        }
    }

    // ---- arrival: make stores visible, count, elect last CTA ----
    __threadfence();
    __syncthreads();
    if (tid == 0)
        s_last = (atomicAdd(&g_done[b], 1) == NCHUNK - 1);
    __syncthreads();
    if (!s_last) return;
    __threadfence();   // acquire side: order counter read before score reads

    // ---- softmax for row b: 256 threads x 4 elements ----
    const int i0 = tid * 4;
    float4 sc = *reinterpret_cast<const float4*>(g_scores + b * L + i0);
    float x0 = (i0 + 0 < len) ? sc.x : -CUDART_INF_F;
    float x1 = (i0 + 1 < len) ? sc.y : -CUDART_INF_F;
    float x2 = (i0 + 2 < len) ? sc.z : -CUDART_INF_F;
    float x3 = (i0 + 3 < len) ? sc.w : -CUDART_INF_F;

    float m = fmaxf(fmaxf(x0, x1), fmaxf(x2, x3));
    #pragma unroll
    for (int o = 16; o; o >>= 1)
        m = fmaxf(m, __shfl_down_sync(0xffffffffu, m, o));
    if (lane == 0) s_red[warp] = m;
    __syncthreads();
    if (warp == 0) {
        float t = (lane < 8) ? s_red[lane] : -CUDART_INF_F;
        #pragma unroll
        for (int o = 4; o; o >>= 1)
            t = fmaxf(t, __shfl_down_sync(0xffffffffu, t, o));
        if (lane == 0) s_bcast = t;
    }
    __syncthreads();
    const float rowmax = s_bcast;

    float e0 = (i0 + 0 < len) ? __expf(x0 - rowmax) : 0.f;
    float e1 = (i0 + 1 < len) ? __expf(x1 - rowmax) : 0.f;
    float e2 = (i0 + 2 < len) ? __expf(x2 - rowmax) : 0.f;
    float e3 = (i0 + 3 < len) ? __expf(x3 - rowmax) : 0.f;

    float s = e0 + e1 + e2 + e3;
    #pragma unroll
    for (int o = 16; o; o >>= 1)
        s += __shfl_down_sync(0xffffffffu, s, o);
    __syncthreads();
    if (lane == 0) s_red[warp] = s;
    __syncthreads();
    if (warp == 0) {
        float t = (lane < 8) ? s_red[lane] : 0.f;
        #pragma unroll
        for (int o = 4; o; o >>= 1)
            t += __shfl_down_sync(0xffffffffu, t, o);
        if (lane == 0) s_bcast = t;
    }
    __syncthreads();
    const float inv = 1.f / s_bcast;

    float4 r = make_float4(e0 * inv, e1 * inv, e2 * inv, e3 * inv);
    *reinterpret_cast<float4*>(out + (size_t)b * L + i0) = r;
}

extern "C" void kernel_launch(void* const* d_in, const int* in_sizes, int n_in,
                              void* d_out, int out_size) {
    const float* questions = (const float*)d_in[0];   // [B2, L, E]
    const int*   lens      = (const int*)d_in[1];     // [B2]
    const float* W         = (const float*)d_in[2];   // [E, E]
    const float* bias      = (const float*)d_in[3];   // [E]
    const float* wv        = (const float*)d_in[4];   // [E, 1]
    float* out             = (float*)d_out;           // [B2, L]

    prep_partial<<<128, 128>>>(W, wv);
    prep_reduce<<<4, 128>>>(bias, wv);
    dim3 sgrid(NCHUNK, B2);
    scores_kernel<<<sgrid, 256>>>(questions, lens, out);
}